// round 2
// baseline (speedup 1.0000x reference)
#include <cuda_runtime.h>
#include <math.h>

#define BATCH 65536
#define DIM   256
#define NF    16     // attention hidden
#define NK    8      // pred hidden

// dynamic shared layout (floats):
//  [0, 8192)        att_w1 transposed  [16][512]
//  [8192, 14336)    pred_w1 transposed [8][768]
//  [14336, 14400)   smalls
#define SW1_OFF   0
#define SWP_OFF   8192
#define SSM_OFF   14336
#define SMEM_FLOATS 14400
#define SMEM_BYTES (SMEM_FLOATS * 4)

// smalls offsets within ssm
//  [0:16)  att_b1   [16:32) att_w2   [32] att_b2
//  [33] cls_w0 [34] cls_w1 [35] cls_b0 [36] cls_b1
//  [37:45) pred_b1  [45:53) pred_w2  [53] pred_b2

__device__ __forceinline__ float dot4(float4 a, float4 b) {
    return a.x * b.x + a.y * b.y + a.z * b.z + a.w * b.w;
}

__global__ __launch_bounds__(128)
void agree_kernel(
    const int*   __restrict__ group_inputs,
    const int*   __restrict__ item_inputs,
    const int*   __restrict__ group_members,
    const float* __restrict__ user_emb,
    const float* __restrict__ item_emb,
    const float* __restrict__ group_emb,
    const float* __restrict__ att_w1,
    const float* __restrict__ att_b1,
    const float* __restrict__ att_w2,
    const float* __restrict__ att_b2,
    const float* __restrict__ cls_w,
    const float* __restrict__ cls_b,
    const float* __restrict__ pred_w1,
    const float* __restrict__ pred_b1,
    const float* __restrict__ pred_w2,
    const float* __restrict__ pred_b2,
    float*       __restrict__ out)
{
    extern __shared__ float sm[];
    float* sw1 = sm + SW1_OFF;   // [16][512]
    float* swp = sm + SWP_OFF;   // [8][768]
    float* ssm = sm + SSM_OFF;

    const int tid = threadIdx.x;

    // stage att_w1 transposed: sw1[f*512 + d] = att_w1[d*16 + f]
    for (int i = tid; i < 512 * NF; i += blockDim.x) {
        int d = i >> 4, f = i & 15;
        sw1[f * 512 + d] = att_w1[i];
    }
    // stage pred_w1 transposed: swp[k*768 + j] = pred_w1[j*8 + k]
    for (int i = tid; i < 768 * NK; i += blockDim.x) {
        int j = i >> 3, k = i & 7;
        swp[k * 768 + j] = pred_w1[i];
    }
    if (tid < NF) {
        ssm[tid]      = att_b1[tid];
        ssm[16 + tid] = att_w2[tid];
    }
    if (tid < NK) {
        ssm[37 + tid] = pred_b1[tid];
        ssm[45 + tid] = pred_w2[tid];
    }
    if (tid == 0) {
        ssm[32] = att_b2[0];
        ssm[33] = cls_w[0];  ssm[34] = cls_w[1];
        ssm[35] = cls_b[0];  ssm[36] = cls_b[1];
        ssm[53] = pred_b2[0];
    }
    __syncthreads();

    const int lane  = tid & 31;
    const int warp  = tid >> 5;
    const int gwarp = blockIdx.x * (blockDim.x >> 5) + warp;
    const int nwarp = gridDim.x * (blockDim.x >> 5);

    for (int b = gwarp; b < BATCH; b += nwarp) {
        const int gid = group_inputs[b];
        const int iid = item_inputs[b];
        const int4 mid4 = *(const int4*)(group_members + gid * 4);
        int mids[4] = {mid4.x, mid4.y, mid4.z, mid4.w};

        // gather rows: lane owns d = {4*lane..+3, 128+4*lane..+3}
        float4 mem[4][2], it[2], grp[2];
        #pragma unroll
        for (int s = 0; s < 4; s++) {
            const float4* row = (const float4*)(user_emb + (size_t)mids[s] * DIM);
            mem[s][0] = row[lane];
            mem[s][1] = row[32 + lane];
        }
        {
            const float4* row = (const float4*)(item_emb + (size_t)iid * DIM);
            it[0] = row[lane];  it[1] = row[32 + lane];
        }
        {
            const float4* row = (const float4*)(group_emb + (size_t)gid * DIM);
            grp[0] = row[lane]; grp[1] = row[32 + lane];
        }

        // ---- attention MLP partials ----
        float acc[4][NF];
        float accI[NF];
        #pragma unroll
        for (int f = 0; f < NF; f++) {
            accI[f] = 0.f;
            #pragma unroll
            for (int s = 0; s < 4; s++) acc[s][f] = 0.f;
        }

        #pragma unroll
        for (int g = 0; g < 2; g++) {
            const int dbase = g * 128 + 4 * lane;
            #pragma unroll
            for (int f = 0; f < NF; f++) {
                float4 wm = *(const float4*)(sw1 + f * 512 + dbase);
                float4 wi = *(const float4*)(sw1 + f * 512 + 256 + dbase);
                accI[f] += dot4(it[g], wi);
                #pragma unroll
                for (int s = 0; s < 4; s++)
                    acc[s][f] += dot4(mem[s][g], wm);
            }
        }
        // fold item contribution into each member slot before reduction
        #pragma unroll
        for (int s = 0; s < 4; s++)
            #pragma unroll
            for (int f = 0; f < NF; f++)
                acc[s][f] += accI[f];

        // butterfly reduce 64 values over the warp
        #pragma unroll
        for (int off = 16; off > 0; off >>= 1) {
            #pragma unroll
            for (int s = 0; s < 4; s++)
                #pragma unroll
                for (int f = 0; f < NF; f++)
                    acc[s][f] += __shfl_xor_sync(0xffffffffu, acc[s][f], off);
        }

        // ---- logits (all lanes compute redundantly) ----
        float b2v = ssm[32];
        float logit[4] = {b2v, b2v, b2v, b2v};
        #pragma unroll
        for (int f = 0; f < NF; f++) {
            float bf  = ssm[f];
            float w2f = ssm[16 + f];
            #pragma unroll
            for (int s = 0; s < 4; s++) {
                float h = fmaxf(acc[s][f] + bf, 0.f);
                logit[s] += h * w2f;
            }
        }

        // argmax (first occurrence) + softmax
        float mx = logit[0]; int idx = 0;
        #pragma unroll
        for (int s = 1; s < 4; s++)
            if (logit[s] > mx) { mx = logit[s]; idx = s; }

        float e[4], sum = 0.f;
        #pragma unroll
        for (int s = 0; s < 4; s++) { e[s] = expf(logit[s] - mx); sum += e[s]; }
        float inv = 1.f / sum;
        float wt[4];
        #pragma unroll
        for (int s = 0; s < 4; s++) wt[s] = e[s] * inv;

        // wt[idx] == exp(0)/sum == inv exactly
        float wtm = inv;
        float s0 = wtm * ssm[33] + ssm[35];
        float s1 = wtm * ssm[34] + ssm[36];
        int pc = (s1 > s0) ? 1 : 0;

        // one-hot-or-softmax coefficients (leader select is exact: 1*x + 0*y)
        float cw[4];
        #pragma unroll
        for (int s = 0; s < 4; s++)
            cw[s] = pc ? ((s == idx) ? 1.f : 0.f) : wt[s];

        // g = g_att + group_emb ; elem = g * item
        float4 gv[2], el[2];
        #pragma unroll
        for (int g = 0; g < 2; g++) {
            float4 v;
            v.x = cw[0]*mem[0][g].x + cw[1]*mem[1][g].x + cw[2]*mem[2][g].x + cw[3]*mem[3][g].x;
            v.y = cw[0]*mem[0][g].y + cw[1]*mem[1][g].y + cw[2]*mem[2][g].y + cw[3]*mem[3][g].y;
            v.z = cw[0]*mem[0][g].z + cw[1]*mem[1][g].z + cw[2]*mem[2][g].z + cw[3]*mem[3][g].z;
            v.w = cw[0]*mem[0][g].w + cw[1]*mem[1][g].w + cw[2]*mem[2][g].w + cw[3]*mem[3][g].w;
            v.x += grp[g].x; v.y += grp[g].y; v.z += grp[g].z; v.w += grp[g].w;
            gv[g] = v;
            el[g] = make_float4(v.x * it[g].x, v.y * it[g].y, v.z * it[g].z, v.w * it[g].w);
        }

        // ---- prediction MLP partials ----
        float acc2[NK];
        #pragma unroll
        for (int k = 0; k < NK; k++) acc2[k] = 0.f;

        #pragma unroll
        for (int g = 0; g < 2; g++) {
            const int dbase = g * 128 + 4 * lane;
            #pragma unroll
            for (int k = 0; k < NK; k++) {
                float4 w0 = *(const float4*)(swp + k * 768 + dbase);
                float4 w1 = *(const float4*)(swp + k * 768 + 256 + dbase);
                float4 w2 = *(const float4*)(swp + k * 768 + 512 + dbase);
                acc2[k] += dot4(el[g], w0) + dot4(gv[g], w1) + dot4(it[g], w2);
            }
        }
        #pragma unroll
        for (int off = 16; off > 0; off >>= 1) {
            #pragma unroll
            for (int k = 0; k < NK; k++)
                acc2[k] += __shfl_xor_sync(0xffffffffu, acc2[k], off);
        }

        if (lane == 0) {
            float z = ssm[53];
            #pragma unroll
            for (int k = 0; k < NK; k++) {
                float h = fmaxf(acc2[k] + ssm[37 + k], 0.f);
                z += h * ssm[45 + k];
            }
            float y = 1.f / (1.f + expf(-z));

            out[b] = y;
            *(float4*)(out + BATCH + 4 * b) = make_float4(wt[0], wt[1], wt[2], wt[3]);
            out[5 * BATCH + b] = (float)pc;
        }
    }
}

extern "C" void kernel_launch(void* const* d_in, const int* in_sizes, int n_in,
                              void* d_out, int out_size)
{
    (void)in_sizes; (void)n_in; (void)out_size;
    cudaFuncSetAttribute(agree_kernel,
                         cudaFuncAttributeMaxDynamicSharedMemorySize, SMEM_BYTES);
    agree_kernel<<<1024, 128, SMEM_BYTES>>>(
        (const int*)d_in[0],  (const int*)d_in[1],  (const int*)d_in[2],
        (const float*)d_in[3], (const float*)d_in[4], (const float*)d_in[5],
        (const float*)d_in[6], (const float*)d_in[7], (const float*)d_in[8],
        (const float*)d_in[9], (const float*)d_in[10], (const float*)d_in[11],
        (const float*)d_in[12], (const float*)d_in[13], (const float*)d_in[14],
        (const float*)d_in[15],
        (float*)d_out);
}

// round 3
// speedup vs baseline: 1.1464x; 1.1464x over previous
#include <cuda_runtime.h>
#include <math.h>

#define BATCH 65536
#define DIM   256
#define NF    16     // attention hidden
#define NK    8      // pred hidden

// dynamic shared layout (floats):
//  [0, 8192)        att_w1 transposed  [16][512]
//  [8192, 14336)    pred_w1 transposed [8][768]
#define SW1_OFF   0
#define SWP_OFF   8192
#define SMEM_FLOATS 14336
#define SMEM_BYTES (SMEM_FLOATS * 4)   // 57344 B -> 4 blocks/SM fits 228KB

#define FULLM 0xffffffffu

__device__ __forceinline__ float dot4(float4 a, float4 b) {
    return a.x * b.x + a.y * b.y + a.z * b.z + a.w * b.w;
}

__global__ __launch_bounds__(128, 4)
void agree_kernel(
    const int*   __restrict__ group_inputs,
    const int*   __restrict__ item_inputs,
    const int*   __restrict__ group_members,
    const float* __restrict__ user_emb,
    const float* __restrict__ item_emb,
    const float* __restrict__ group_emb,
    const float* __restrict__ att_w1,
    const float* __restrict__ att_b1,
    const float* __restrict__ att_w2,
    const float* __restrict__ att_b2,
    const float* __restrict__ cls_w,
    const float* __restrict__ cls_b,
    const float* __restrict__ pred_w1,
    const float* __restrict__ pred_b1,
    const float* __restrict__ pred_w2,
    const float* __restrict__ pred_b2,
    float*       __restrict__ out)
{
    extern __shared__ float sm[];
    float* sw1 = sm + SW1_OFF;   // [16][512]
    float* swp = sm + SWP_OFF;   // [8][768]

    const int tid = threadIdx.x;

    // stage att_w1 transposed: sw1[f*512 + d] = att_w1[d*16 + f]
    for (int i = tid; i < 512 * NF; i += blockDim.x) {
        int d = i >> 4, f = i & 15;
        sw1[f * 512 + d] = att_w1[i];
    }
    // stage pred_w1 transposed: swp[k*768 + j] = pred_w1[j*8 + k]
    for (int i = tid; i < 768 * NK; i += blockDim.x) {
        int j = i >> 3, k = i & 7;
        swp[k * 768 + j] = pred_w1[i];
    }
    __syncthreads();

    const int lane  = tid & 31;
    const int warp  = tid >> 5;
    const int gwarp = blockIdx.x * (blockDim.x >> 5) + warp;
    const int nwarp = gridDim.x * (blockDim.x >> 5);

    // per-lane constants (loop invariant, loaded once from global)
    const int fi_l = lane & 7;
    const float b1a = __ldg(att_b1 + fi_l);
    const float b1b = __ldg(att_b1 + 8 + fi_l);
    const float w2a = __ldg(att_w2 + fi_l);
    const float w2b = __ldg(att_w2 + 8 + fi_l);
    const float pbk = __ldg(pred_b1 + fi_l);
    const float pwk = __ldg(pred_w2 + fi_l);
    const float b2v = __ldg(att_b2);
    const float clw0 = __ldg(cls_w), clw1 = __ldg(cls_w + 1);
    const float clb0 = __ldg(cls_b), clb1 = __ldg(cls_b + 1);
    const float pb2  = __ldg(pred_b2);

    for (int b = gwarp; b < BATCH; b += nwarp) {
        const int gid = group_inputs[b];
        const int iid = item_inputs[b];
        const int4 mid4 = *(const int4*)(group_members + gid * 4);
        int mids[4] = {mid4.x, mid4.y, mid4.z, mid4.w};

        // gather rows: lane owns d = {4*lane..+3, 128+4*lane..+3}
        float4 mem[4][2], it[2];
        #pragma unroll
        for (int s = 0; s < 4; s++) {
            const float4* row = (const float4*)(user_emb + (size_t)mids[s] * DIM);
            mem[s][0] = row[lane];
            mem[s][1] = row[32 + lane];
        }
        {
            const float4* row = (const float4*)(item_emb + (size_t)iid * DIM);
            it[0] = row[lane];  it[1] = row[32 + lane];
        }

        // ---- attention MLP, f chunked by 8, fold-reduced ----
        float logit_loc = b2v;   // per-group-of-8-lanes partial logit
        #pragma unroll
        for (int c = 0; c < 2; c++) {
            float A[32];   // value v = s*8+fi (this lane's partial)
            #pragma unroll
            for (int fi = 0; fi < 8; fi++) {
                const float* wrow = sw1 + (c * 8 + fi) * 512;
                float4 wm0 = *(const float4*)(wrow + 4 * lane);
                float4 wm1 = *(const float4*)(wrow + 128 + 4 * lane);
                float4 wi0 = *(const float4*)(wrow + 256 + 4 * lane);
                float4 wi1 = *(const float4*)(wrow + 384 + 4 * lane);
                float itp = dot4(it[0], wi0) + dot4(it[1], wi1);
                #pragma unroll
                for (int s = 0; s < 4; s++)
                    A[s * 8 + fi] = dot4(mem[s][0], wm0) + dot4(mem[s][1], wm1) + itp;
            }
            // fold: 32 values x 32 lanes -> lane v holds total of value v
            #pragma unroll
            for (int d = 16; d >= 1; d >>= 1) {
                const bool hi = (lane & d) != 0;
                #pragma unroll
                for (int i = 0; i < d; i++) {
                    float send = hi ? A[i] : A[i + d];
                    float recv = __shfl_xor_sync(FULLM, send, d);
                    A[i] = (hi ? A[i + d] : A[i]) + recv;
                }
            }
            // lane: s = lane>>3, f = c*8 + (lane&7)
            float bc = c ? b1b : b1a;
            float wc = c ? w2b : w2a;
            float cv = fmaxf(A[0] + bc, 0.f) * wc;
            cv += __shfl_xor_sync(FULLM, cv, 1);
            cv += __shfl_xor_sync(FULLM, cv, 2);
            cv += __shfl_xor_sync(FULLM, cv, 4);
            logit_loc += cv;
        }
        float logit[4];
        #pragma unroll
        for (int s = 0; s < 4; s++)
            logit[s] = __shfl_sync(FULLM, logit_loc, s * 8);

        // argmax (first occurrence) + softmax
        float mx = logit[0]; int idx = 0;
        #pragma unroll
        for (int s = 1; s < 4; s++)
            if (logit[s] > mx) { mx = logit[s]; idx = s; }

        float e[4], sum = 0.f;
        #pragma unroll
        for (int s = 0; s < 4; s++) { e[s] = expf(logit[s] - mx); sum += e[s]; }
        float inv = 1.f / sum;
        float wt[4];
        #pragma unroll
        for (int s = 0; s < 4; s++) wt[s] = e[s] * inv;

        // wt[idx] == exp(0)/sum == inv exactly
        float s0 = inv * clw0 + clb0;
        float s1 = inv * clw1 + clb1;
        int pc = (s1 > s0) ? 1 : 0;

        // one-hot-or-softmax coefficients (leader select exact: 1*x + 0*y)
        float cw[4];
        #pragma unroll
        for (int s = 0; s < 4; s++)
            cw[s] = pc ? ((s == idx) ? 1.f : 0.f) : wt[s];

        // g = g_att + group_emb ; elem = g * item
        const float4* grow = (const float4*)(group_emb + (size_t)gid * DIM);
        float4 gv[2], el[2];
        #pragma unroll
        for (int g = 0; g < 2; g++) {
            float4 grp = grow[g * 32 + lane];
            float4 v;
            v.x = cw[0]*mem[0][g].x + cw[1]*mem[1][g].x + cw[2]*mem[2][g].x + cw[3]*mem[3][g].x;
            v.y = cw[0]*mem[0][g].y + cw[1]*mem[1][g].y + cw[2]*mem[2][g].y + cw[3]*mem[3][g].y;
            v.z = cw[0]*mem[0][g].z + cw[1]*mem[1][g].z + cw[2]*mem[2][g].z + cw[3]*mem[3][g].z;
            v.w = cw[0]*mem[0][g].w + cw[1]*mem[1][g].w + cw[2]*mem[2][g].w + cw[3]*mem[3][g].w;
            v.x += grp.x; v.y += grp.y; v.z += grp.z; v.w += grp.w;
            gv[g] = v;
            el[g] = make_float4(v.x * it[g].x, v.y * it[g].y, v.z * it[g].z, v.w * it[g].w);
        }

        // ---- prediction MLP partials ----
        float A2[NK];
        #pragma unroll
        for (int k = 0; k < NK; k++) {
            const float* wr = swp + k * 768;
            float4 w0 = *(const float4*)(wr + 4 * lane);
            float4 w1 = *(const float4*)(wr + 128 + 4 * lane);
            float4 w2_ = *(const float4*)(wr + 256 + 4 * lane);
            float4 w3 = *(const float4*)(wr + 384 + 4 * lane);
            float4 w4 = *(const float4*)(wr + 512 + 4 * lane);
            float4 w5 = *(const float4*)(wr + 640 + 4 * lane);
            A2[k] = dot4(el[0], w0) + dot4(el[1], w1)
                  + dot4(gv[0], w2_) + dot4(gv[1], w3)
                  + dot4(it[0], w4) + dot4(it[1], w5);
        }
        // fold 8 values -> lane holds k = lane&7 (partial over octet)
        #pragma unroll
        for (int d = 4; d >= 1; d >>= 1) {
            const bool hi = (lane & d) != 0;
            #pragma unroll
            for (int i = 0; i < d; i++) {
                float send = hi ? A2[i] : A2[i + d];
                float recv = __shfl_xor_sync(FULLM, send, d);
                A2[i] = (hi ? A2[i + d] : A2[i]) + recv;
            }
        }
        float v2 = A2[0];
        v2 += __shfl_xor_sync(FULLM, v2, 8);
        v2 += __shfl_xor_sync(FULLM, v2, 16);
        // v2 = full acc for k = lane&7
        float hz = fmaxf(v2 + pbk, 0.f) * pwk;
        hz += __shfl_xor_sync(FULLM, hz, 1);
        hz += __shfl_xor_sync(FULLM, hz, 2);
        hz += __shfl_xor_sync(FULLM, hz, 4);

        if (lane == 0) {
            float z = hz + pb2;
            float y = 1.f / (1.f + expf(-z));
            out[b] = y;
            *(float4*)(out + BATCH + 4 * b) = make_float4(wt[0], wt[1], wt[2], wt[3]);
            out[5 * BATCH + b] = (float)pc;
        }
    }
}

extern "C" void kernel_launch(void* const* d_in, const int* in_sizes, int n_in,
                              void* d_out, int out_size)
{
    (void)in_sizes; (void)n_in; (void)out_size;
    cudaFuncSetAttribute(agree_kernel,
                         cudaFuncAttributeMaxDynamicSharedMemorySize, SMEM_BYTES);
    agree_kernel<<<1024, 128, SMEM_BYTES>>>(
        (const int*)d_in[0],  (const int*)d_in[1],  (const int*)d_in[2],
        (const float*)d_in[3], (const float*)d_in[4], (const float*)d_in[5],
        (const float*)d_in[6], (const float*)d_in[7], (const float*)d_in[8],
        (const float*)d_in[9], (const float*)d_in[10], (const float*)d_in[11],
        (const float*)d_in[12], (const float*)d_in[13], (const float*)d_in[14],
        (const float*)d_in[15],
        (float*)d_out);
}

// round 4
// speedup vs baseline: 1.9271x; 1.6809x over previous
#include <cuda_runtime.h>
#include <cuda_bf16.h>
#include <math.h>

#define BATCH 65536
#define NPAIR 32768
#define DIM   256
#define FULLM 0xffffffffu

// smem: att_w1 transposed [16][512] fp32 (32768B) + pred_w1 packed bf16 (12288B)
#define SW1_FLOATS (16 * 512)
#define SWP_HALFS  (8 * 3 * 256)
#define SMEM_BYTES (SW1_FLOATS * 4 + SWP_HALFS * 2)   // 45056 B

__device__ __forceinline__ float dot4(float4 a, float4 b) {
    return a.x * b.x + a.y * b.y + a.z * b.z + a.w * b.w;
}

// fold 16 values across 32 lanes -> every lane returns full sum of value (lane&15)
__device__ __forceinline__ float fold16(float* A, int lane) {
    #pragma unroll
    for (int d = 8; d >= 1; d >>= 1) {
        const bool hi = (lane & d) != 0;
        #pragma unroll
        for (int i = 0; i < d; i++) {
            float send = hi ? A[i] : A[i + d];
            float recv = __shfl_xor_sync(FULLM, send, d);
            A[i] = (hi ? A[i + d] : A[i]) + recv;
        }
    }
    float v = A[0];
    v += __shfl_xor_sync(FULLM, v, 16);
    return v;
}

// fold 8 values across 32 lanes -> every lane returns full sum of value (lane&7)
__device__ __forceinline__ float fold8(float* A, int lane) {
    #pragma unroll
    for (int d = 4; d >= 1; d >>= 1) {
        const bool hi = (lane & d) != 0;
        #pragma unroll
        for (int i = 0; i < d; i++) {
            float send = hi ? A[i] : A[i + d];
            float recv = __shfl_xor_sync(FULLM, send, d);
            A[i] = (hi ? A[i + d] : A[i]) + recv;
        }
    }
    float v = A[0];
    v += __shfl_xor_sync(FULLM, v, 8);
    v += __shfl_xor_sync(FULLM, v, 16);
    return v;
}

__global__ __launch_bounds__(128, 3)
void agree_kernel(
    const int*   __restrict__ group_inputs,
    const int*   __restrict__ item_inputs,
    const int*   __restrict__ group_members,
    const float* __restrict__ user_emb,
    const float* __restrict__ item_emb,
    const float* __restrict__ group_emb,
    const float* __restrict__ att_w1,
    const float* __restrict__ att_b1,
    const float* __restrict__ att_w2,
    const float* __restrict__ att_b2,
    const float* __restrict__ cls_w,
    const float* __restrict__ cls_b,
    const float* __restrict__ pred_w1,
    const float* __restrict__ pred_b1,
    const float* __restrict__ pred_w2,
    const float* __restrict__ pred_b2,
    float*       __restrict__ out)
{
    extern __shared__ float sm[];
    float* sw1 = sm;                                        // [16][512] fp32
    __nv_bfloat16* swp = (__nv_bfloat16*)(sm + SW1_FLOATS); // packed bf16

    const int tid = threadIdx.x;

    // stage att_w1 transposed: sw1[f*512 + d] = att_w1[d*16 + f]
    for (int i = tid; i < 512 * 16; i += blockDim.x) {
        int d = i >> 4, f = i & 15;
        sw1[f * 512 + d] = att_w1[i];
    }
    // stage pred_w1 as bf16, custom packed:
    //  half index = k*768 + r*256 + lane*8 + ii
    //  source j = r*256 + (ii>=4 ? 128 : 0) + 4*lane + (ii&3), value pred_w1[j*8+k]
    for (int i = tid; i < SWP_HALFS; i += blockDim.x) {
        int k   = i / 768;
        int rem = i - k * 768;
        int r   = rem >> 8;
        int q   = rem & 255;
        int ln  = q >> 3;
        int ii  = q & 7;
        int j   = r * 256 + ((ii & 4) ? 128 : 0) + 4 * ln + (ii & 3);
        swp[i] = __float2bfloat16(pred_w1[j * 8 + k]);
    }
    __syncthreads();

    const int lane  = tid & 31;
    const int gwarp = blockIdx.x * 4 + (tid >> 5);
    const int nwarp = gridDim.x * 4;

    // per-lane constants
    const int l3 = lane & 3;
    float b1c[4], w2c[4];
    #pragma unroll
    for (int c = 0; c < 4; c++) {
        b1c[c] = __ldg(att_b1 + c * 4 + l3);
        w2c[c] = __ldg(att_w2 + c * 4 + l3);
    }
    const float pbk  = __ldg(pred_b1 + (lane & 7));
    const float pwk  = __ldg(pred_w2 + (lane & 7));
    const float b2v  = __ldg(att_b2);
    const float clw0 = __ldg(cls_w), clw1 = __ldg(cls_w + 1);
    const float clb0 = __ldg(cls_b), clb1 = __ldg(cls_b + 1);
    const float pb2  = __ldg(pred_b2);

    for (int p = gwarp; p < NPAIR; p += nwarp) {
        int gid[2], iid[2];
        float4 mem[2][4][2], it[2][2];
        #pragma unroll
        for (int e = 0; e < 2; e++) {
            const int b = 2 * p + e;
            gid[e] = group_inputs[b];
            iid[e] = item_inputs[b];
            const int4 m4 = *(const int4*)(group_members + gid[e] * 4);
            int mids[4] = {m4.x, m4.y, m4.z, m4.w};
            #pragma unroll
            for (int s = 0; s < 4; s++) {
                const float4* row = (const float4*)(user_emb + (size_t)mids[s] * DIM);
                mem[e][s][0] = row[lane];
                mem[e][s][1] = row[32 + lane];
            }
            const float4* irow = (const float4*)(item_emb + (size_t)iid[e] * DIM);
            it[e][0] = irow[lane];
            it[e][1] = irow[32 + lane];
        }

        // ---- attention MLP: f chunked by 4, weights shared across both elements ----
        float logit_loc[2] = {b2v, b2v};
        #pragma unroll
        for (int c = 0; c < 4; c++) {
            float A0[16], A1[16];
            #pragma unroll
            for (int fi = 0; fi < 4; fi++) {
                const float* wrow = sw1 + (c * 4 + fi) * 512;
                float4 wm0 = *(const float4*)(wrow + 4 * lane);
                float4 wm1 = *(const float4*)(wrow + 128 + 4 * lane);
                float4 wi0 = *(const float4*)(wrow + 256 + 4 * lane);
                float4 wi1 = *(const float4*)(wrow + 384 + 4 * lane);
                float itp0 = dot4(it[0][0], wi0) + dot4(it[0][1], wi1);
                float itp1 = dot4(it[1][0], wi0) + dot4(it[1][1], wi1);
                #pragma unroll
                for (int s = 0; s < 4; s++) {
                    A0[s * 4 + fi] = dot4(mem[0][s][0], wm0) + dot4(mem[0][s][1], wm1) + itp0;
                    A1[s * 4 + fi] = dot4(mem[1][s][0], wm0) + dot4(mem[1][s][1], wm1) + itp1;
                }
            }
            // fold -> lane holds value (lane&15): s = (lane&15)>>2, fi = lane&3
            {
                float r0 = fold16(A0, lane);
                float cv = fmaxf(r0 + b1c[c], 0.f) * w2c[c];
                cv += __shfl_xor_sync(FULLM, cv, 1);
                cv += __shfl_xor_sync(FULLM, cv, 2);
                logit_loc[0] += cv;
            }
            {
                float r1 = fold16(A1, lane);
                float cv = fmaxf(r1 + b1c[c], 0.f) * w2c[c];
                cv += __shfl_xor_sync(FULLM, cv, 1);
                cv += __shfl_xor_sync(FULLM, cv, 2);
                logit_loc[1] += cv;
            }
        }

        // broadcast logits (lane s*4 holds logit of member s)
        float wt[2][4];
        int   pc[2], idx[2];
        float cw[2][4];
        #pragma unroll
        for (int e = 0; e < 2; e++) {
            float logit[4];
            #pragma unroll
            for (int s = 0; s < 4; s++)
                logit[s] = __shfl_sync(FULLM, logit_loc[e], s * 4);

            float mx = logit[0]; int ix = 0;
            #pragma unroll
            for (int s = 1; s < 4; s++)
                if (logit[s] > mx) { mx = logit[s]; ix = s; }
            idx[e] = ix;

            float ev[4], sum = 0.f;
            #pragma unroll
            for (int s = 0; s < 4; s++) { ev[s] = expf(logit[s] - mx); sum += ev[s]; }
            float inv = 1.f / sum;
            #pragma unroll
            for (int s = 0; s < 4; s++) wt[e][s] = ev[s] * inv;

            // wt[idx] == inv exactly
            float s0 = inv * clw0 + clb0;
            float s1 = inv * clw1 + clb1;
            pc[e] = (s1 > s0) ? 1 : 0;
            #pragma unroll
            for (int s = 0; s < 4; s++)
                cw[e][s] = pc[e] ? ((s == ix) ? 1.f : 0.f) : wt[e][s];
        }

        // g = g_att + group_emb ; elem = g * item
        float4 gv[2][2], el[2][2];
        #pragma unroll
        for (int e = 0; e < 2; e++) {
            const float4* grow = (const float4*)(group_emb + (size_t)gid[e] * DIM);
            #pragma unroll
            for (int g = 0; g < 2; g++) {
                float4 grp = grow[g * 32 + lane];
                float4 v;
                v.x = cw[e][0]*mem[e][0][g].x + cw[e][1]*mem[e][1][g].x + cw[e][2]*mem[e][2][g].x + cw[e][3]*mem[e][3][g].x;
                v.y = cw[e][0]*mem[e][0][g].y + cw[e][1]*mem[e][1][g].y + cw[e][2]*mem[e][2][g].y + cw[e][3]*mem[e][3][g].y;
                v.z = cw[e][0]*mem[e][0][g].z + cw[e][1]*mem[e][1][g].z + cw[e][2]*mem[e][2][g].z + cw[e][3]*mem[e][3][g].z;
                v.w = cw[e][0]*mem[e][0][g].w + cw[e][1]*mem[e][1][g].w + cw[e][2]*mem[e][2][g].w + cw[e][3]*mem[e][3][g].w;
                v.x += grp.x; v.y += grp.y; v.z += grp.z; v.w += grp.w;
                gv[e][g] = v;
                el[e][g] = make_float4(v.x * it[e][g].x, v.y * it[e][g].y,
                                       v.z * it[e][g].z, v.w * it[e][g].w);
            }
        }

        // ---- prediction MLP: bf16 packed weights, shared across both elements ----
        float A20[8], A21[8];
        #pragma unroll
        for (int k = 0; k < 8; k++) {
            float acc0 = 0.f, acc1 = 0.f;
            #pragma unroll
            for (int r = 0; r < 3; r++) {
                uint4 u = *(const uint4*)(swp + (k * 3 + r) * 256 + lane * 8);
                const __nv_bfloat162* h2 = (const __nv_bfloat162*)&u;
                float2 p0 = __bfloat1622float2(h2[0]);
                float2 p1 = __bfloat1622float2(h2[1]);
                float2 p2 = __bfloat1622float2(h2[2]);
                float2 p3 = __bfloat1622float2(h2[3]);
                #pragma unroll
                for (int e = 0; e < 2; e++) {
                    float4 v0 = (r == 0) ? el[e][0] : (r == 1) ? gv[e][0] : it[e][0];
                    float4 v1 = (r == 0) ? el[e][1] : (r == 1) ? gv[e][1] : it[e][1];
                    float a = p0.x * v0.x + p0.y * v0.y + p1.x * v0.z + p1.y * v0.w
                            + p2.x * v1.x + p2.y * v1.y + p3.x * v1.z + p3.y * v1.w;
                    if (e == 0) acc0 += a; else acc1 += a;
                }
            }
            A20[k] = acc0;
            A21[k] = acc1;
        }

        float y[2];
        #pragma unroll
        for (int e = 0; e < 2; e++) {
            float v = fold8(e == 0 ? A20 : A21, lane);   // full acc for k = lane&7
            float hz = fmaxf(v + pbk, 0.f) * pwk;
            hz += __shfl_xor_sync(FULLM, hz, 1);
            hz += __shfl_xor_sync(FULLM, hz, 2);
            hz += __shfl_xor_sync(FULLM, hz, 4);
            float z = hz + pb2;
            y[e] = 1.f / (1.f + expf(-z));
        }

        if (lane < 2) {
            const int e = lane;
            const int b = 2 * p + e;
            out[b] = y[e];
            *(float4*)(out + BATCH + 4 * b) = make_float4(wt[e][0], wt[e][1], wt[e][2], wt[e][3]);
            out[5 * BATCH + b] = (float)pc[e];
        }
    }
}

extern "C" void kernel_launch(void* const* d_in, const int* in_sizes, int n_in,
                              void* d_out, int out_size)
{
    (void)in_sizes; (void)n_in; (void)out_size;
    cudaFuncSetAttribute(agree_kernel,
                         cudaFuncAttributeMaxDynamicSharedMemorySize, SMEM_BYTES);
    agree_kernel<<<444, 128, SMEM_BYTES>>>(
        (const int*)d_in[0],  (const int*)d_in[1],  (const int*)d_in[2],
        (const float*)d_in[3], (const float*)d_in[4], (const float*)d_in[5],
        (const float*)d_in[6], (const float*)d_in[7], (const float*)d_in[8],
        (const float*)d_in[9], (const float*)d_in[10], (const float*)d_in[11],
        (const float*)d_in[12], (const float*)d_in[13], (const float*)d_in[14],
        (const float*)d_in[15],
        (float*)d_out);
}